// round 16
// baseline (speedup 1.0000x reference)
#include <cuda_runtime.h>
#include <cuda_fp16.h>
#include <cstdint>
#include <math.h>

// ---------------------------------------------------------------------------
// R-NEM cell — full fp16 m16n8k16 pipeline (fp32 accumulate).
// R16: unified fragment array g_ap[mtg][96] (s1 | eff | x, x packed in cvtw);
//      k_out = uniform barrier-free 96-kt loop, M=32/CTA, 3 CTAs/SM, grid 512.
// core_pre[v] = U[p] + V[q] + core_b, [U|V] = s1 @ core_w (packed k-major)
// ---------------------------------------------------------------------------

#define FCN   256
#define LASTN 128
#define HDIM  512
#define MDIM  1024
#define NR1   16384
#define NR2   114688
#define KOUT  (2 * FCN + MDIM)
#define NKTG  (KOUT / 16)   // 96

__device__ float g_uv[NR1 * 2 * FCN];

// fragment-packed fp16 A for k_out: [mtg(1024)][ktg(96)] blocks of 512 B
//   ktg 0..15 = s1, 16..31 = effect, 32..95 = x ; lane*16 = a0..a3
__device__ __align__(16) uint4 g_ap[(NR1 / 16) * NKTG * 32];   // 48 MB

// fp16 fragment-packed weights: slot = (kt16 * (N/16) + n16) * 32 + lane
__device__ __align__(16) uint4 g_wencp4[(HDIM / 16) * (FCN / 16) * 32];
__device__ __align__(16) uint4 g_wuvp4 [(FCN / 16) * (2 * FCN / 16) * 32];
__device__ __align__(16) uint4 g_woutp4[(KOUT / 16) * (FCN / 16) * 32];
__device__ __align__(16) uint4 g_wattp4[(FCN / 16) * (LASTN / 16) * 32];
__device__ __align__(16) uint4 g_wctxp4[(FCN / 16) * (FCN / 16) * 32];

// -------------------------------- helpers ---------------------------------
__device__ __forceinline__ void mma16(float* c, const unsigned* a, const unsigned* b) {
    asm volatile(
        "mma.sync.aligned.m16n8k16.row.col.f32.f16.f16.f32 "
        "{%0,%1,%2,%3}, {%4,%5,%6,%7}, {%8,%9}, {%0,%1,%2,%3};"
        : "+f"(c[0]), "+f"(c[1]), "+f"(c[2]), "+f"(c[3])
        : "r"(a[0]), "r"(a[1]), "r"(a[2]), "r"(a[3]), "r"(b[0]), "r"(b[1]));
}
__device__ __forceinline__ unsigned packh(float a, float b) {
    __half2 h = __floats2half2_rn(a, b);
    return *(unsigned*)&h;
}
__device__ __forceinline__ float tanh_ax(float x) {
    float y; asm("tanh.approx.f32 %0, %1;" : "=f"(y) : "f"(x)); return y;
}
__device__ __forceinline__ float sigmoid_ax(float x) {
    float e; asm("ex2.approx.f32 %0, %1;" : "=f"(e) : "f"(-x * 1.4426950408889634f));
    return 1.f / (1.f + e);
}
// Pack one float4 (row, col..col+3) into fragment-layout A buffer (smem).
__device__ __forceinline__ void packA(char* buf, int nkt, int row, int col, float4 v) {
    int mt = row >> 4, hm = (row >> 3) & 1, gg = row & 7;
    int kt = col >> 4;
    int p0 = (col & 15) >> 1;
    char* blk = buf + (mt * nkt + kt) * 528;
    int tt0 = p0 & 3, hk0 = p0 >> 2;
    int p1 = p0 + 1, tt1 = p1 & 3, hk1 = p1 >> 2;
    *(unsigned*)(blk + ((gg << 2) + tt0) * 16 + (hk0 * 2 + hm) * 4) = packh(v.x, v.y);
    *(unsigned*)(blk + ((gg << 2) + tt1) * 16 + (hk1 * 2 + hm) * 4) = packh(v.z, v.w);
}
__device__ __forceinline__ void packA2(char* buf, int nkt, int row, int col,
                                       float o0, float o1) {
    int mt = row >> 4, hm = (row >> 3) & 1, gg = row & 7;
    int kt = col >> 4;
    int p0 = (col & 15) >> 1;
    int tt = p0 & 3, hk = p0 >> 2;
    *(unsigned*)(buf + (mt * nkt + kt) * 528 + ((gg << 2) + tt) * 16
                 + (hk * 2 + hm) * 4) = packh(o0, o1);
}
// Pack a single (row-in-16, even col) pair into the GLOBAL fragment array.
__device__ __forceinline__ void packG(int mtg, int ktg, int rowin, int col, unsigned val) {
    int gg = rowin & 7, hm = rowin >> 3;
    int p0 = (col & 15) >> 1, tt = p0 & 3, hk = p0 >> 2;
    char* base = (char*)g_ap + ((size_t)mtg * NKTG + ktg) * 512
               + ((gg << 2) + tt) * 16 + (hk * 2 + hm) * 4;
    *(unsigned*)base = val;
}

// ---------------------------------------------------------------------------
// Kernel 0: pack weights AND x into fp16 fragment layout
// ---------------------------------------------------------------------------
__global__ void k_cvtw(const float* __restrict__ enc_w, const float* __restrict__ core_w,
                       const float* __restrict__ ctx_w, const float* __restrict__ att1_w,
                       const float* __restrict__ out_w, const float* __restrict__ xin)
{
    int i = blockIdx.x * blockDim.x + threadIdx.x;
    int n = gridDim.x * blockDim.x;

    // x -> g_ap ktg 32..95  (dominant cost; do first)
    for (int idx = i; idx < (NR1/16) * 64 * 32; idx += n) {
        int mtg = idx >> 11;              // /(64*32)
        int rem = idx & 2047;
        int ktg = rem >> 5, lane = rem & 31;
        int gg = lane >> 2, tt = lane & 3;
        const float* r0 = xin + (size_t)(mtg * 16 + gg) * MDIM + ktg * 16;
        const float* r1 = r0 + 8 * MDIM;
        float2 v00 = *(const float2*)(r0 + 2 * tt);
        float2 v10 = *(const float2*)(r1 + 2 * tt);
        float2 v01 = *(const float2*)(r0 + 8 + 2 * tt);
        float2 v11 = *(const float2*)(r1 + 8 + 2 * tt);
        g_ap[((size_t)mtg * NKTG + 32 + ktg) * 32 + lane] =
            make_uint4(packh(v00.x, v00.y), packh(v10.x, v10.y),
                       packh(v01.x, v01.y), packh(v11.x, v11.y));
    }
    for (int idx = i; idx < (HDIM/16) * (FCN/16) * 32; idx += n) {
        int kt = idx / ((FCN/16) * 32);
        int rem = idx - kt * ((FCN/16) * 32);
        int n16 = rem >> 5, lane = rem & 31;
        int gg = lane >> 2, tt = lane & 3;
        int na = n16 * 16 + gg, nb = na + 8, k0 = kt * 16;
        g_wencp4[idx] = make_uint4(
            packh(enc_w[(k0+2*tt)*FCN+na],   enc_w[(k0+2*tt+1)*FCN+na]),
            packh(enc_w[(k0+8+2*tt)*FCN+na], enc_w[(k0+9+2*tt)*FCN+na]),
            packh(enc_w[(k0+2*tt)*FCN+nb],   enc_w[(k0+2*tt+1)*FCN+nb]),
            packh(enc_w[(k0+8+2*tt)*FCN+nb], enc_w[(k0+9+2*tt)*FCN+nb]));
    }
    for (int idx = i; idx < (FCN/16) * (2*FCN/16) * 32; idx += n) {
        int kt = idx / ((2*FCN/16) * 32);
        int rem = idx - kt * ((2*FCN/16) * 32);
        int n16 = rem >> 5, lane = rem & 31;
        int gg = lane >> 2, tt = lane & 3;
        int na = n16 * 16 + gg, nb = na + 8, k0 = kt * 16;
        #define GUV(k,c) ((c) < FCN ? core_w[(k)*FCN+(c)] : core_w[(FCN+(k))*FCN+((c)-FCN)])
        g_wuvp4[idx] = make_uint4(
            packh(GUV(k0+2*tt,na),   GUV(k0+2*tt+1,na)),
            packh(GUV(k0+8+2*tt,na), GUV(k0+9+2*tt,na)),
            packh(GUV(k0+2*tt,nb),   GUV(k0+2*tt+1,nb)),
            packh(GUV(k0+8+2*tt,nb), GUV(k0+9+2*tt,nb)));
        #undef GUV
    }
    for (int idx = i; idx < (KOUT/16) * (FCN/16) * 32; idx += n) {
        int kt = idx / ((FCN/16) * 32);
        int rem = idx - kt * ((FCN/16) * 32);
        int n16 = rem >> 5, lane = rem & 31;
        int gg = lane >> 2, tt = lane & 3;
        int na = n16 * 16 + gg, nb = na + 8, k0 = kt * 16;
        g_woutp4[idx] = make_uint4(
            packh(out_w[(k0+2*tt)*FCN+na],   out_w[(k0+2*tt+1)*FCN+na]),
            packh(out_w[(k0+8+2*tt)*FCN+na], out_w[(k0+9+2*tt)*FCN+na]),
            packh(out_w[(k0+2*tt)*FCN+nb],   out_w[(k0+2*tt+1)*FCN+nb]),
            packh(out_w[(k0+8+2*tt)*FCN+nb], out_w[(k0+9+2*tt)*FCN+nb]));
    }
    for (int idx = i; idx < (FCN/16) * (LASTN/16) * 32; idx += n) {
        int kt = idx / ((LASTN/16) * 32);
        int rem = idx - kt * ((LASTN/16) * 32);
        int n16 = rem >> 5, lane = rem & 31;
        int gg = lane >> 2, tt = lane & 3;
        int na = n16 * 16 + gg, nb = na + 8, k0 = kt * 16;
        g_wattp4[idx] = make_uint4(
            packh(att1_w[(k0+2*tt)*LASTN+na],   att1_w[(k0+2*tt+1)*LASTN+na]),
            packh(att1_w[(k0+8+2*tt)*LASTN+na], att1_w[(k0+9+2*tt)*LASTN+na]),
            packh(att1_w[(k0+2*tt)*LASTN+nb],   att1_w[(k0+2*tt+1)*LASTN+nb]),
            packh(att1_w[(k0+8+2*tt)*LASTN+nb], att1_w[(k0+9+2*tt)*LASTN+nb]));
    }
    for (int idx = i; idx < (FCN/16) * (FCN/16) * 32; idx += n) {
        int kt = idx / ((FCN/16) * 32);
        int rem = idx - kt * ((FCN/16) * 32);
        int n16 = rem >> 5, lane = rem & 31;
        int gg = lane >> 2, tt = lane & 3;
        int na = n16 * 16 + gg, nb = na + 8, k0 = kt * 16;
        g_wctxp4[idx] = make_uint4(
            packh(ctx_w[(k0+2*tt)*FCN+na],   ctx_w[(k0+2*tt+1)*FCN+na]),
            packh(ctx_w[(k0+8+2*tt)*FCN+na], ctx_w[(k0+9+2*tt)*FCN+na]),
            packh(ctx_w[(k0+2*tt)*FCN+nb],   ctx_w[(k0+2*tt+1)*FCN+nb]),
            packh(ctx_w[(k0+8+2*tt)*FCN+nb], ctx_w[(k0+9+2*tt)*FCN+nb]));
    }
}

// ---------------------------------------------------------------------------
// Kernel 1 (fused): s1 = relu(LN(state @ enc_w + b)) then [U|V] = s1 @ Wuv.
// Epilogue writes s1 fragments into g_ap (ktg 0..15).
// ---------------------------------------------------------------------------
__global__ __launch_bounds__(256, 2) void k_encuv(
    const float* __restrict__ state, const float* __restrict__ bias,
    const float* __restrict__ gam, const float* __restrict__ bet)
{
    extern __shared__ float sm[];
    char*   sAuv = (char*)sm;                 // 33792 B (uv A tile, 4mt x 16kt)
    float2* red  = (float2*)(sAuv + 33792);   // [4][64]
    char*   sSt  = sAuv;                      // enc staging: 2 x 8448 B (alias)

    const int tid = threadIdx.x;
    const int wid = tid >> 5, lane = tid & 31;
    const int g = lane >> 2, t = lane & 3;
    const int wm = wid & 1, wn = wid >> 1;
    const int R0 = blockIdx.x * 64;

    int rp[4], fp[4];
#pragma unroll
    for (int p = 0; p < 4; p++) {
        int idx = tid + 256 * p;
        rp[p] = idx >> 4; fp[p] = (idx & 15) * 4;
    }

    float c[2][8][4];
#pragma unroll
    for (int mt = 0; mt < 2; mt++)
#pragma unroll
        for (int nt = 0; nt < 8; nt++)
#pragma unroll
            for (int e = 0; e < 4; e++) c[mt][nt][e] = 0.f;

    float4 av[4];
#pragma unroll
    for (int p = 0; p < 4; p++)
        av[p] = *(const float4*)&state[(size_t)(R0 + rp[p]) * HDIM + fp[p]];
#pragma unroll
    for (int p = 0; p < 4; p++) packA(sSt, 4, rp[p], fp[p], av[p]);
    __syncthreads();

    const int T = HDIM / 64;   // 8 chunks
    for (int ch = 0; ch < T; ch++) {
        char* cur = sSt + (ch & 1) * 8448;
        if (ch + 1 < T) {
#pragma unroll
            for (int p = 0; p < 4; p++)
                av[p] = *(const float4*)&state[(size_t)(R0 + rp[p]) * HDIM
                                               + (ch + 1) * 64 + fp[p]];
        }
#pragma unroll
        for (int ktl = 0; ktl < 4; ktl++) {
            unsigned a[2][4];
#pragma unroll
            for (int mt = 0; mt < 2; mt++) {
                uint4 q = *(uint4*)(cur + ((wm * 2 + mt) * 4 + ktl) * 528 + lane * 16);
                a[mt][0] = q.x; a[mt][1] = q.y; a[mt][2] = q.z; a[mt][3] = q.w;
            }
            int ktg = ch * 4 + ktl;
#pragma unroll
            for (int nt2 = 0; nt2 < 4; nt2++) {
                uint4 bv = __ldg(&g_wencp4[(size_t)(ktg * 16 + wn * 4 + nt2) * 32 + lane]);
                unsigned bl[2] = {bv.x, bv.y}, bh[2] = {bv.z, bv.w};
                mma16(c[0][2*nt2],   a[0], bl);
                mma16(c[1][2*nt2],   a[1], bl);
                mma16(c[0][2*nt2+1], a[0], bh);
                mma16(c[1][2*nt2+1], a[1], bh);
            }
        }
        if (ch + 1 < T) {
            char* nxt = sSt + ((ch + 1) & 1) * 8448;
#pragma unroll
            for (int p = 0; p < 4; p++) packA(nxt, 4, rp[p], fp[p], av[p]);
        }
        __syncthreads();
    }

#pragma unroll
    for (int nt = 0; nt < 8; nt++) {
        int col = wn * 64 + nt * 8 + 2 * t;
        float b0 = __ldg(&bias[col]), b1 = __ldg(&bias[col + 1]);
#pragma unroll
        for (int mt = 0; mt < 2; mt++) {
            c[mt][nt][0] += b0; c[mt][nt][1] += b1;
            c[mt][nt][2] += b0; c[mt][nt][3] += b1;
        }
    }
#pragma unroll
    for (int mt = 0; mt < 2; mt++) {
        float s0 = 0, q0 = 0, s1v = 0, q1 = 0;
#pragma unroll
        for (int nt = 0; nt < 8; nt++) {
            s0 += c[mt][nt][0] + c[mt][nt][1];
            q0 += c[mt][nt][0] * c[mt][nt][0] + c[mt][nt][1] * c[mt][nt][1];
            s1v += c[mt][nt][2] + c[mt][nt][3];
            q1 += c[mt][nt][2] * c[mt][nt][2] + c[mt][nt][3] * c[mt][nt][3];
        }
#pragma unroll
        for (int o = 1; o <= 2; o <<= 1) {
            s0 += __shfl_xor_sync(~0u, s0, o); q0 += __shfl_xor_sync(~0u, q0, o);
            s1v += __shfl_xor_sync(~0u, s1v, o); q1 += __shfl_xor_sync(~0u, q1, o);
        }
        if (t == 0) {
            red[wn * 64 + wm * 32 + mt * 16 + g]     = make_float2(s0, q0);
            red[wn * 64 + wm * 32 + mt * 16 + g + 8] = make_float2(s1v, q1);
        }
    }
    __syncthreads();
#pragma unroll
    for (int mt = 0; mt < 2; mt++)
#pragma unroll
        for (int h = 0; h < 2; h++) {
            int row = wm * 32 + mt * 16 + g + 8 * h;
            float s = 0, q = 0;
#pragma unroll
            for (int w2 = 0; w2 < 4; w2++) {
                float2 r2 = red[w2 * 64 + row]; s += r2.x; q += r2.y;
            }
            float mu = s * (1.f / FCN);
            float rs = rsqrtf(q * (1.f / FCN) - mu * mu + 1e-5f);
#pragma unroll
            for (int nt = 0; nt < 8; nt++) {
                int col = wn * 64 + nt * 8 + 2 * t;
                float o0 = fmaxf((c[mt][nt][2*h]   - mu) * rs * __ldg(&gam[col])   + __ldg(&bet[col]),   0.f);
                float o1 = fmaxf((c[mt][nt][2*h+1] - mu) * rs * __ldg(&gam[col+1]) + __ldg(&bet[col+1]), 0.f);
                packA2(sAuv, 16, row, col, o0, o1);
                packG((R0 + row) >> 4, col >> 4, row & 15, col, packh(o0, o1));
            }
        }
    __syncthreads();

    for (int half = 0; half < 2; half++) {
        float cu[2][8][4];
#pragma unroll
        for (int mt = 0; mt < 2; mt++)
#pragma unroll
            for (int nt = 0; nt < 8; nt++)
#pragma unroll
                for (int e = 0; e < 4; e++) cu[mt][nt][e] = 0.f;

#pragma unroll 4
        for (int kt = 0; kt < 16; kt++) {
            unsigned a[2][4];
#pragma unroll
            for (int mt = 0; mt < 2; mt++) {
                uint4 q = *(uint4*)(sAuv + ((wm * 2 + mt) * 16 + kt) * 528 + lane * 16);
                a[mt][0] = q.x; a[mt][1] = q.y; a[mt][2] = q.z; a[mt][3] = q.w;
            }
#pragma unroll
            for (int nt2 = 0; nt2 < 4; nt2++) {
                uint4 bv = __ldg(&g_wuvp4[(size_t)(kt * 32 + half * 16 + wn * 4 + nt2) * 32 + lane]);
                unsigned bl[2] = {bv.x, bv.y}, bh[2] = {bv.z, bv.w};
                mma16(cu[0][2*nt2],   a[0], bl);
                mma16(cu[1][2*nt2],   a[1], bl);
                mma16(cu[0][2*nt2+1], a[0], bh);
                mma16(cu[1][2*nt2+1], a[1], bh);
            }
        }
#pragma unroll
        for (int mt = 0; mt < 2; mt++)
#pragma unroll
            for (int h = 0; h < 2; h++) {
                int row = R0 + wm * 32 + mt * 16 + g + 8 * h;
#pragma unroll
                for (int nt = 0; nt < 8; nt++) {
                    int col = half * 256 + wn * 64 + nt * 8 + 2 * t;
                    *(float2*)&g_uv[(size_t)row * 512 + col] =
                        make_float2(cu[mt][nt][2*h], cu[mt][nt][2*h+1]);
                }
            }
    }
}

// ---------------------------------------------------------------------------
// Kernel 3 (fp16): k_eff — R10 winner; effect store -> g_ap ktg 16..31.
// ---------------------------------------------------------------------------
__global__ __launch_bounds__(256, 3) void k_eff(
    const float* __restrict__ core_b, const float* __restrict__ core_g,
    const float* __restrict__ core_bb,
    const float* __restrict__ ctx_b,
    const float* __restrict__ ctx_g, const float* __restrict__ ctx_bb,
    const float* __restrict__ a1_b,
    const float* __restrict__ att_g, const float* __restrict__ att_bb,
    const float* __restrict__ a2W,  const float* __restrict__ a2_b)
{
    extern __shared__ float sm[];
    char*     sAp   = (char*)sm;
    unsigned* sCtx2 = (unsigned*)(sAp + 33792);
    float2*   sRed  = (float2*)(sCtx2 + 64 * 132);
    float*    sDot  = (float*)(sRed + 4 * 64);
    float*    sAtt  = sDot + 4 * 64;
    float2*   sMu   = (float2*)(sAtt + 64);

    const int tid = threadIdx.x;
    const int wid = tid >> 5, lane = tid & 31;
    const int g = lane >> 2, t = lane & 3;
    const int wm = wid & 1, wn = wid >> 1;
    const int R0 = blockIdx.x * 56;
    const int NKT = FCN / 16;

    {
        float* z = (float*)(sAp + 3 * 16 * 528);
        for (int i = tid; i < 16 * 528 / 4; i += 256) z[i] = 0.f;
    }
    __syncthreads();

    {
#pragma unroll
        for (int rr = 0; rr < 7; rr++) {
            int lrow = wid * 7 + rr;
            int v = R0 + lrow;
            int p = v / 7;
            int jj = v - p * 7;
            int i = p & 7;
            int j = jj + (jj >= i ? 1 : 0);
            int q = (p & ~7) + j;
            float2 val[4];
            float s = 0.f, s2 = 0.f;
#pragma unroll
            for (int e = 0; e < 4; e++) {
                int col = 2 * lane + 64 * e;
                float2 u  = *(const float2*)&g_uv[(size_t)p * 512 + col];
                float2 vq = *(const float2*)&g_uv[(size_t)q * 512 + 256 + col];
                float2 cb = *(const float2*)&core_b[col];
                val[e].x = u.x + vq.x + cb.x;
                val[e].y = u.y + vq.y + cb.y;
                s += val[e].x + val[e].y;
                s2 += val[e].x * val[e].x + val[e].y * val[e].y;
            }
#pragma unroll
            for (int o = 16; o; o >>= 1) {
                s  += __shfl_xor_sync(~0u, s,  o);
                s2 += __shfl_xor_sync(~0u, s2, o);
            }
            float mu = s * (1.f / FCN);
            float rs = rsqrtf(s2 * (1.f / FCN) - mu * mu + 1e-5f);
            int mtile = lrow >> 4, gg = lrow & 7, hm = (lrow >> 3) & 1;
            int tt = lane & 3, hk = (lane >> 2) & 1;
#pragma unroll
            for (int e = 0; e < 4; e++) {
                int col = 2 * lane + 64 * e;
                float2 cg = *(const float2*)&core_g[col];
                float2 cbb = *(const float2*)&core_bb[col];
                float o0 = fmaxf((val[e].x - mu) * rs * cg.x + cbb.x, 0.f);
                float o1 = fmaxf((val[e].y - mu) * rs * cg.y + cbb.y, 0.f);
                int kt = (lane >> 3) + 4 * e;
                unsigned off = (unsigned)((mtile * 16 + kt) * 528
                                          + ((gg << 2) + tt) * 16 + (hk * 2 + hm) * 4);
                *(unsigned*)(sAp + off) = packh(o0, o1);
            }
        }
    }
    __syncthreads();

    {
        float ca[2][4][4];
#pragma unroll
        for (int mt = 0; mt < 2; mt++)
#pragma unroll
            for (int nt = 0; nt < 4; nt++)
#pragma unroll
                for (int e = 0; e < 4; e++) ca[mt][nt][e] = 0.f;

#pragma unroll
        for (int kt = 0; kt < NKT; kt++) {
            unsigned a[2][4];
#pragma unroll
            for (int mt = 0; mt < 2; mt++) {
                uint4 q = *(uint4*)(sAp + ((wm * 2 + mt) * 16 + kt) * 528 + lane * 16);
                a[mt][0] = q.x; a[mt][1] = q.y; a[mt][2] = q.z; a[mt][3] = q.w;
            }
#pragma unroll
            for (int nt2 = 0; nt2 < 2; nt2++) {
                uint4 bv = __ldg(&g_wattp4[(size_t)(kt * 8 + wn * 2 + nt2) * 32 + lane]);
                unsigned bl[2] = {bv.x, bv.y}, bh[2] = {bv.z, bv.w};
                mma16(ca[0][2*nt2],   a[0], bl);
                mma16(ca[1][2*nt2],   a[1], bl);
                mma16(ca[0][2*nt2+1], a[0], bh);
                mma16(ca[1][2*nt2+1], a[1], bh);
            }
        }
#pragma unroll
        for (int nt = 0; nt < 4; nt++) {
            int col = wn * 32 + nt * 8 + 2 * t;
            float b0 = __ldg(&a1_b[col]), b1 = __ldg(&a1_b[col + 1]);
#pragma unroll
            for (int mt = 0; mt < 2; mt++) {
                ca[mt][nt][0] += b0; ca[mt][nt][1] += b1;
                ca[mt][nt][2] += b0; ca[mt][nt][3] += b1;
            }
        }
#pragma unroll
        for (int mt = 0; mt < 2; mt++) {
            float s0 = 0, q0 = 0, s1v = 0, q1 = 0;
#pragma unroll
            for (int nt = 0; nt < 4; nt++) {
                s0 += ca[mt][nt][0] + ca[mt][nt][1];
                q0 += ca[mt][nt][0] * ca[mt][nt][0] + ca[mt][nt][1] * ca[mt][nt][1];
                s1v += ca[mt][nt][2] + ca[mt][nt][3];
                q1 += ca[mt][nt][2] * ca[mt][nt][2] + ca[mt][nt][3] * ca[mt][nt][3];
            }
#pragma unroll
            for (int o = 1; o <= 2; o <<= 1) {
                s0 += __shfl_xor_sync(~0u, s0, o); q0 += __shfl_xor_sync(~0u, q0, o);
                s1v += __shfl_xor_sync(~0u, s1v, o); q1 += __shfl_xor_sync(~0u, q1, o);
            }
            if (t == 0) {
                sRed[wn * 64 + wm * 32 + mt * 16 + g]     = make_float2(s0, q0);
                sRed[wn * 64 + wm * 32 + mt * 16 + g + 8] = make_float2(s1v, q1);
            }
        }
        __syncthreads();
#pragma unroll
        for (int mt = 0; mt < 2; mt++)
#pragma unroll
            for (int h = 0; h < 2; h++) {
                int row = wm * 32 + mt * 16 + g + 8 * h;
                float s = 0, q = 0;
#pragma unroll
                for (int w2 = 0; w2 < 4; w2++) {
                    float2 r2 = sRed[w2 * 64 + row]; s += r2.x; q += r2.y;
                }
                float mu = s * (1.f / LASTN);
                float rs = rsqrtf(q * (1.f / LASTN) - mu * mu + 1e-5f);
                float d = 0.f;
#pragma unroll
                for (int nt = 0; nt < 4; nt++) {
                    int col = wn * 32 + nt * 8 + 2 * t;
                    float gg0 = __ldg(&att_g[col]),   bb0 = __ldg(&att_bb[col]),   w0 = __ldg(&a2W[col]);
                    float gg1 = __ldg(&att_g[col+1]), bb1 = __ldg(&att_bb[col+1]), w1 = __ldg(&a2W[col+1]);
                    d += tanh_ax((ca[mt][nt][2*h]   - mu) * rs * gg0 + bb0) * w0;
                    d += tanh_ax((ca[mt][nt][2*h+1] - mu) * rs * gg1 + bb1) * w1;
                }
#pragma unroll
                for (int o = 1; o <= 2; o <<= 1) d += __shfl_xor_sync(~0u, d, o);
                if (t == 0) sDot[wn * 64 + row] = d;
            }
        __syncthreads();
        if (wid < 2) {
            int row = wid * 32 + lane;
            float a2b = __ldg(&a2_b[0]);
            float d = sDot[row] + sDot[64 + row] + sDot[128 + row] + sDot[192 + row];
            sAtt[row] = sigmoid_ax(d + a2b);
        }
        __syncthreads();
    }

    for (int half = 0; half < 2; half++) {
        float cc[2][4][4];
#pragma unroll
        for (int mt = 0; mt < 2; mt++)
#pragma unroll
            for (int nt = 0; nt < 4; nt++)
#pragma unroll
                for (int e = 0; e < 4; e++) cc[mt][nt][e] = 0.f;

#pragma unroll
        for (int kt = 0; kt < NKT; kt++) {
            unsigned a[2][4];
#pragma unroll
            for (int mt = 0; mt < 2; mt++) {
                uint4 q = *(uint4*)(sAp + ((wm * 2 + mt) * 16 + kt) * 528 + lane * 16);
                a[mt][0] = q.x; a[mt][1] = q.y; a[mt][2] = q.z; a[mt][3] = q.w;
            }
#pragma unroll
            for (int nt2 = 0; nt2 < 2; nt2++) {
                uint4 bv = __ldg(&g_wctxp4[(size_t)(kt * 16 + half * 8 + wn * 2 + nt2) * 32 + lane]);
                unsigned bl[2] = {bv.x, bv.y}, bh[2] = {bv.z, bv.w};
                mma16(cc[0][2*nt2],   a[0], bl);
                mma16(cc[1][2*nt2],   a[1], bl);
                mma16(cc[0][2*nt2+1], a[0], bh);
                mma16(cc[1][2*nt2+1], a[1], bh);
            }
        }
#pragma unroll
        for (int mt = 0; mt < 2; mt++)
#pragma unroll
            for (int nt = 0; nt < 4; nt++) {
                int col = half * 128 + wn * 32 + nt * 8 + 2 * t;
                float b0 = __ldg(&ctx_b[col]), b1 = __ldg(&ctx_b[col + 1]);
                int r0 = wm * 32 + mt * 16 + g;
                int ci = col >> 1;
                sCtx2[r0 * 132 + ci]       = packh(cc[mt][nt][0] + b0, cc[mt][nt][1] + b1);
                sCtx2[(r0 + 8) * 132 + ci] = packh(cc[mt][nt][2] + b0, cc[mt][nt][3] + b1);
            }
    }
    __syncthreads();

    {
        int r = tid >> 2, b = tid & 3;
        float s = 0.f, q = 0.f;
        if (r < 56) {
#pragma unroll
            for (int j = 0; j < 32; j++) {
                __half2 h = *(__half2*)&sCtx2[r * 132 + b + 4 * j];
                float2 f = __half22float2(h);
                s += f.x + f.y; q += f.x * f.x + f.y * f.y;
            }
        }
        s += __shfl_xor_sync(~0u, s, 1); q += __shfl_xor_sync(~0u, q, 1);
        s += __shfl_xor_sync(~0u, s, 2); q += __shfl_xor_sync(~0u, q, 2);
        if (b == 0 && r < 56) {
            float mu = s * (1.f / FCN);
            float rs = rsqrtf(q * (1.f / FCN) - mu * mu + 1e-5f);
            sMu[r] = make_float2(mu, rs);
        }
    }
    __syncthreads();

    for (int s0 = tid; s0 < 8 * 128; s0 += 256) {
        int gg = s0 >> 7, c2 = s0 & 127;
        float2 gm = __ldg((const float2*)&ctx_g[2 * c2]);
        float2 bb = __ldg((const float2*)&ctx_bb[2 * c2]);
        float e0 = 0.f, e1 = 0.f;
        int rb = gg * 7;
#pragma unroll
        for (int rr = 0; rr < 7; rr++) {
            int r = rb + rr;
            float2 mr = sMu[r];
            float at = sAtt[r];
            float2 f = __half22float2(*(__half2*)&sCtx2[r * 132 + c2]);
            e0 += fmaxf((f.x - mr.x) * mr.y * gm.x + bb.x, 0.f) * at;
            e1 += fmaxf((f.y - mr.x) * mr.y * gm.y + bb.y, 0.f) * at;
        }
        int grow = blockIdx.x * 8 + gg;
        packG(grow >> 4, 16 + (c2 >> 3), grow & 15, 2 * c2, packh(e0, e1));
    }
}

// ---------------------------------------------------------------------------
// Kernel 4 (fp16): new_state = concat(s1, effect, x) @ out_w + out_b
// R16: uniform barrier-free 96-kt loop over packed g_ap. M=32/CTA,
// 3 CTAs/SM, grid 512. Warps 2 (rows) x 4 (cols); warp = 16 x 64.
// ---------------------------------------------------------------------------
__global__ __launch_bounds__(256, 3) void k_out(
    const float* __restrict__ bias, float* __restrict__ out, int dup)
{
    const int tid = threadIdx.x;
    const int wid = tid >> 5, lane = tid & 31;
    const int g = lane >> 2, t = lane & 3;
    const int wm = wid & 1, wn = wid >> 1;
    const int R0 = blockIdx.x * 32;
    const int mtg = (R0 >> 4) + wm;

    float c[8][4];
#pragma unroll
    for (int nt = 0; nt < 8; nt++)
#pragma unroll
        for (int e = 0; e < 4; e++) c[nt][e] = 0.f;

#pragma unroll 8
    for (int ktg = 0; ktg < NKTG; ktg++) {
        uint4 q = __ldg(&g_ap[((size_t)mtg * NKTG + ktg) * 32 + lane]);
        unsigned a[4] = {q.x, q.y, q.z, q.w};
#pragma unroll
        for (int nt2 = 0; nt2 < 4; nt2++) {
            uint4 bv = __ldg(&g_woutp4[(size_t)(ktg * 16 + wn * 4 + nt2) * 32 + lane]);
            unsigned bl[2] = {bv.x, bv.y}, bh[2] = {bv.z, bv.w};
            mma16(c[2*nt2],   a, bl);
            mma16(c[2*nt2+1], a, bh);
        }
    }

#pragma unroll
    for (int h = 0; h < 2; h++) {
        int row = R0 + wm * 16 + g + 8 * h;
#pragma unroll
        for (int nt = 0; nt < 8; nt++) {
            int col = wn * 64 + nt * 8 + 2 * t;
            float o0 = c[nt][2*h]   + __ldg(&bias[col]);
            float o1 = c[nt][2*h+1] + __ldg(&bias[col + 1]);
            size_t off = (size_t)row * FCN + col;
            *(float2*)&out[off] = make_float2(o0, o1);
            if (dup) *(float2*)&out[(size_t)NR1 * FCN + off] = make_float2(o0, o1);
        }
    }
}

// ---------------------------------------------------------------------------
extern "C" void kernel_launch(void* const* d_in, const int* in_sizes, int n_in,
                              void* d_out, int out_size) {
    const float* x      = (const float*)d_in[0];
    const float* state  = (const float*)d_in[1];
    const float* enc_w  = (const float*)d_in[2];
    const float* enc_b  = (const float*)d_in[3];
    const float* enc_g  = (const float*)d_in[4];
    const float* enc_bb = (const float*)d_in[5];
    const float* core_w = (const float*)d_in[6];
    const float* core_b = (const float*)d_in[7];
    const float* core_g = (const float*)d_in[8];
    const float* core_bb= (const float*)d_in[9];
    const float* ctx_w  = (const float*)d_in[10];
    const float* ctx_b  = (const float*)d_in[11];
    const float* ctx_g  = (const float*)d_in[12];
    const float* ctx_bb = (const float*)d_in[13];
    const float* att1_w = (const float*)d_in[14];
    const float* att1_b = (const float*)d_in[15];
    const float* att_g  = (const float*)d_in[16];
    const float* att_bb = (const float*)d_in[17];
    const float* att2_w = (const float*)d_in[18];
    const float* att2_b = (const float*)d_in[19];
    const float* out_w  = (const float*)d_in[20];
    const float* out_b  = (const float*)d_in[21];
    float* out = (float*)d_out;
    int dup = (out_size >= 2 * NR1 * FCN) ? 1 : 0;

    const int smem_encuv = 33792 + 4 * 64 * 8;
    const int smem_eff   = 33792 + 33792 + 4 * 64 * 8 + 4 * 64 * 4 + 64 * 4 + 64 * 8;

    static int attr_done = 0;
    if (!attr_done) {
        cudaFuncSetAttribute(k_encuv, cudaFuncAttributeMaxDynamicSharedMemorySize, smem_encuv);
        cudaFuncSetAttribute(k_eff,   cudaFuncAttributeMaxDynamicSharedMemorySize, smem_eff);
        attr_done = 1;
    }

    k_cvtw<<<2048, 256>>>(enc_w, core_w, ctx_w, att1_w, out_w, x);
    k_encuv<<<NR1 / 64, 256, smem_encuv>>>(state, enc_b, enc_g, enc_bb);
    k_eff<<<NR2 / 56, 256, smem_eff>>>(core_b, core_g, core_bb,
                                       ctx_b, ctx_g, ctx_bb,
                                       att1_b, att_g, att_bb,
                                       att2_w, att2_b);
    k_out<<<NR1 / 32, 256>>>(out_b, out, dup);
}

// round 17
// speedup vs baseline: 1.2443x; 1.2443x over previous
#include <cuda_runtime.h>
#include <cuda_fp16.h>
#include <cstdint>
#include <math.h>

// ---------------------------------------------------------------------------
// R-NEM cell — full fp16 m16n8k16 pipeline (fp32 accumulate).
// R17: unified g_ap[mtg][96] kept; k_out rebuilt M=64/CTA with explicit
//      register double-buffered A prefetch (distance 2), barrier-free.
// core_pre[v] = U[p] + V[q] + core_b, [U|V] = s1 @ core_w (packed k-major)
// ---------------------------------------------------------------------------

#define FCN   256
#define LASTN 128
#define HDIM  512
#define MDIM  1024
#define NR1   16384
#define NR2   114688
#define KOUT  (2 * FCN + MDIM)
#define NKTG  (KOUT / 16)   // 96

__device__ float g_uv[NR1 * 2 * FCN];

// fragment-packed fp16 A for k_out: [mtg(1024)][ktg(96)] blocks of 512 B
//   ktg 0..15 = s1, 16..31 = effect, 32..95 = x ; lane*16 = a0..a3
__device__ __align__(16) uint4 g_ap[(NR1 / 16) * NKTG * 32];   // 48 MB

// fp16 fragment-packed weights: slot = (kt16 * (N/16) + n16) * 32 + lane
__device__ __align__(16) uint4 g_wencp4[(HDIM / 16) * (FCN / 16) * 32];
__device__ __align__(16) uint4 g_wuvp4 [(FCN / 16) * (2 * FCN / 16) * 32];
__device__ __align__(16) uint4 g_woutp4[(KOUT / 16) * (FCN / 16) * 32];
__device__ __align__(16) uint4 g_wattp4[(FCN / 16) * (LASTN / 16) * 32];
__device__ __align__(16) uint4 g_wctxp4[(FCN / 16) * (FCN / 16) * 32];

// -------------------------------- helpers ---------------------------------
__device__ __forceinline__ void mma16(float* c, const unsigned* a, const unsigned* b) {
    asm volatile(
        "mma.sync.aligned.m16n8k16.row.col.f32.f16.f16.f32 "
        "{%0,%1,%2,%3}, {%4,%5,%6,%7}, {%8,%9}, {%0,%1,%2,%3};"
        : "+f"(c[0]), "+f"(c[1]), "+f"(c[2]), "+f"(c[3])
        : "r"(a[0]), "r"(a[1]), "r"(a[2]), "r"(a[3]), "r"(b[0]), "r"(b[1]));
}
__device__ __forceinline__ unsigned packh(float a, float b) {
    __half2 h = __floats2half2_rn(a, b);
    return *(unsigned*)&h;
}
__device__ __forceinline__ float tanh_ax(float x) {
    float y; asm("tanh.approx.f32 %0, %1;" : "=f"(y) : "f"(x)); return y;
}
__device__ __forceinline__ float sigmoid_ax(float x) {
    float e; asm("ex2.approx.f32 %0, %1;" : "=f"(e) : "f"(-x * 1.4426950408889634f));
    return 1.f / (1.f + e);
}
// Pack one float4 (row, col..col+3) into fragment-layout A buffer (smem).
__device__ __forceinline__ void packA(char* buf, int nkt, int row, int col, float4 v) {
    int mt = row >> 4, hm = (row >> 3) & 1, gg = row & 7;
    int kt = col >> 4;
    int p0 = (col & 15) >> 1;
    char* blk = buf + (mt * nkt + kt) * 528;
    int tt0 = p0 & 3, hk0 = p0 >> 2;
    int p1 = p0 + 1, tt1 = p1 & 3, hk1 = p1 >> 2;
    *(unsigned*)(blk + ((gg << 2) + tt0) * 16 + (hk0 * 2 + hm) * 4) = packh(v.x, v.y);
    *(unsigned*)(blk + ((gg << 2) + tt1) * 16 + (hk1 * 2 + hm) * 4) = packh(v.z, v.w);
}
__device__ __forceinline__ void packA2(char* buf, int nkt, int row, int col,
                                       float o0, float o1) {
    int mt = row >> 4, hm = (row >> 3) & 1, gg = row & 7;
    int kt = col >> 4;
    int p0 = (col & 15) >> 1;
    int tt = p0 & 3, hk = p0 >> 2;
    *(unsigned*)(buf + (mt * nkt + kt) * 528 + ((gg << 2) + tt) * 16
                 + (hk * 2 + hm) * 4) = packh(o0, o1);
}
// Pack a single (row-in-16, even col) pair into the GLOBAL fragment array.
__device__ __forceinline__ void packG(int mtg, int ktg, int rowin, int col, unsigned val) {
    int gg = rowin & 7, hm = rowin >> 3;
    int p0 = (col & 15) >> 1, tt = p0 & 3, hk = p0 >> 2;
    char* base = (char*)g_ap + ((size_t)mtg * NKTG + ktg) * 512
               + ((gg << 2) + tt) * 16 + (hk * 2 + hm) * 4;
    *(unsigned*)base = val;
}

// ---------------------------------------------------------------------------
// Kernel 0: pack weights AND x into fp16 fragment layout
// ---------------------------------------------------------------------------
__global__ void k_cvtw(const float* __restrict__ enc_w, const float* __restrict__ core_w,
                       const float* __restrict__ ctx_w, const float* __restrict__ att1_w,
                       const float* __restrict__ out_w, const float* __restrict__ xin)
{
    int i = blockIdx.x * blockDim.x + threadIdx.x;
    int n = gridDim.x * blockDim.x;

    // x -> g_ap ktg 32..95
    for (int idx = i; idx < (NR1/16) * 64 * 32; idx += n) {
        int mtg = idx >> 11;
        int rem = idx & 2047;
        int ktg = rem >> 5, lane = rem & 31;
        int gg = lane >> 2, tt = lane & 3;
        const float* r0 = xin + (size_t)(mtg * 16 + gg) * MDIM + ktg * 16;
        const float* r1 = r0 + 8 * MDIM;
        float2 v00 = *(const float2*)(r0 + 2 * tt);
        float2 v10 = *(const float2*)(r1 + 2 * tt);
        float2 v01 = *(const float2*)(r0 + 8 + 2 * tt);
        float2 v11 = *(const float2*)(r1 + 8 + 2 * tt);
        g_ap[((size_t)mtg * NKTG + 32 + ktg) * 32 + lane] =
            make_uint4(packh(v00.x, v00.y), packh(v10.x, v10.y),
                       packh(v01.x, v01.y), packh(v11.x, v11.y));
    }
    for (int idx = i; idx < (HDIM/16) * (FCN/16) * 32; idx += n) {
        int kt = idx / ((FCN/16) * 32);
        int rem = idx - kt * ((FCN/16) * 32);
        int n16 = rem >> 5, lane = rem & 31;
        int gg = lane >> 2, tt = lane & 3;
        int na = n16 * 16 + gg, nb = na + 8, k0 = kt * 16;
        g_wencp4[idx] = make_uint4(
            packh(enc_w[(k0+2*tt)*FCN+na],   enc_w[(k0+2*tt+1)*FCN+na]),
            packh(enc_w[(k0+8+2*tt)*FCN+na], enc_w[(k0+9+2*tt)*FCN+na]),
            packh(enc_w[(k0+2*tt)*FCN+nb],   enc_w[(k0+2*tt+1)*FCN+nb]),
            packh(enc_w[(k0+8+2*tt)*FCN+nb], enc_w[(k0+9+2*tt)*FCN+nb]));
    }
    for (int idx = i; idx < (FCN/16) * (2*FCN/16) * 32; idx += n) {
        int kt = idx / ((2*FCN/16) * 32);
        int rem = idx - kt * ((2*FCN/16) * 32);
        int n16 = rem >> 5, lane = rem & 31;
        int gg = lane >> 2, tt = lane & 3;
        int na = n16 * 16 + gg, nb = na + 8, k0 = kt * 16;
        #define GUV(k,c) ((c) < FCN ? core_w[(k)*FCN+(c)] : core_w[(FCN+(k))*FCN+((c)-FCN)])
        g_wuvp4[idx] = make_uint4(
            packh(GUV(k0+2*tt,na),   GUV(k0+2*tt+1,na)),
            packh(GUV(k0+8+2*tt,na), GUV(k0+9+2*tt,na)),
            packh(GUV(k0+2*tt,nb),   GUV(k0+2*tt+1,nb)),
            packh(GUV(k0+8+2*tt,nb), GUV(k0+9+2*tt,nb)));
        #undef GUV
    }
    for (int idx = i; idx < (KOUT/16) * (FCN/16) * 32; idx += n) {
        int kt = idx / ((FCN/16) * 32);
        int rem = idx - kt * ((FCN/16) * 32);
        int n16 = rem >> 5, lane = rem & 31;
        int gg = lane >> 2, tt = lane & 3;
        int na = n16 * 16 + gg, nb = na + 8, k0 = kt * 16;
        g_woutp4[idx] = make_uint4(
            packh(out_w[(k0+2*tt)*FCN+na],   out_w[(k0+2*tt+1)*FCN+na]),
            packh(out_w[(k0+8+2*tt)*FCN+na], out_w[(k0+9+2*tt)*FCN+na]),
            packh(out_w[(k0+2*tt)*FCN+nb],   out_w[(k0+2*tt+1)*FCN+nb]),
            packh(out_w[(k0+8+2*tt)*FCN+nb], out_w[(k0+9+2*tt)*FCN+nb]));
    }
    for (int idx = i; idx < (FCN/16) * (LASTN/16) * 32; idx += n) {
        int kt = idx / ((LASTN/16) * 32);
        int rem = idx - kt * ((LASTN/16) * 32);
        int n16 = rem >> 5, lane = rem & 31;
        int gg = lane >> 2, tt = lane & 3;
        int na = n16 * 16 + gg, nb = na + 8, k0 = kt * 16;
        g_wattp4[idx] = make_uint4(
            packh(att1_w[(k0+2*tt)*LASTN+na],   att1_w[(k0+2*tt+1)*LASTN+na]),
            packh(att1_w[(k0+8+2*tt)*LASTN+na], att1_w[(k0+9+2*tt)*LASTN+na]),
            packh(att1_w[(k0+2*tt)*LASTN+nb],   att1_w[(k0+2*tt+1)*LASTN+nb]),
            packh(att1_w[(k0+8+2*tt)*LASTN+nb], att1_w[(k0+9+2*tt)*LASTN+nb]));
    }
    for (int idx = i; idx < (FCN/16) * (FCN/16) * 32; idx += n) {
        int kt = idx / ((FCN/16) * 32);
        int rem = idx - kt * ((FCN/16) * 32);
        int n16 = rem >> 5, lane = rem & 31;
        int gg = lane >> 2, tt = lane & 3;
        int na = n16 * 16 + gg, nb = na + 8, k0 = kt * 16;
        g_wctxp4[idx] = make_uint4(
            packh(ctx_w[(k0+2*tt)*FCN+na],   ctx_w[(k0+2*tt+1)*FCN+na]),
            packh(ctx_w[(k0+8+2*tt)*FCN+na], ctx_w[(k0+9+2*tt)*FCN+na]),
            packh(ctx_w[(k0+2*tt)*FCN+nb],   ctx_w[(k0+2*tt+1)*FCN+nb]),
            packh(ctx_w[(k0+8+2*tt)*FCN+nb], ctx_w[(k0+9+2*tt)*FCN+nb]));
    }
}

// ---------------------------------------------------------------------------
// Kernel 1 (fused): s1 = relu(LN(state @ enc_w + b)) then [U|V] = s1 @ Wuv.
// Epilogue writes s1 fragments into g_ap (ktg 0..15). (unchanged from R16)
// ---------------------------------------------------------------------------
__global__ __launch_bounds__(256, 2) void k_encuv(
    const float* __restrict__ state, const float* __restrict__ bias,
    const float* __restrict__ gam, const float* __restrict__ bet)
{
    extern __shared__ float sm[];
    char*   sAuv = (char*)sm;                 // 33792 B (uv A tile, 4mt x 16kt)
    float2* red  = (float2*)(sAuv + 33792);   // [4][64]
    char*   sSt  = sAuv;                      // enc staging: 2 x 8448 B (alias)

    const int tid = threadIdx.x;
    const int wid = tid >> 5, lane = tid & 31;
    const int g = lane >> 2, t = lane & 3;
    const int wm = wid & 1, wn = wid >> 1;
    const int R0 = blockIdx.x * 64;

    int rp[4], fp[4];
#pragma unroll
    for (int p = 0; p < 4; p++) {
        int idx = tid + 256 * p;
        rp[p] = idx >> 4; fp[p] = (idx & 15) * 4;
    }

    float c[2][8][4];
#pragma unroll
    for (int mt = 0; mt < 2; mt++)
#pragma unroll
        for (int nt = 0; nt < 8; nt++)
#pragma unroll
            for (int e = 0; e < 4; e++) c[mt][nt][e] = 0.f;

    float4 av[4];
#pragma unroll
    for (int p = 0; p < 4; p++)
        av[p] = *(const float4*)&state[(size_t)(R0 + rp[p]) * HDIM + fp[p]];
#pragma unroll
    for (int p = 0; p < 4; p++) packA(sSt, 4, rp[p], fp[p], av[p]);
    __syncthreads();

    const int T = HDIM / 64;   // 8 chunks
    for (int ch = 0; ch < T; ch++) {
        char* cur = sSt + (ch & 1) * 8448;
        if (ch + 1 < T) {
#pragma unroll
            for (int p = 0; p < 4; p++)
                av[p] = *(const float4*)&state[(size_t)(R0 + rp[p]) * HDIM
                                               + (ch + 1) * 64 + fp[p]];
        }
#pragma unroll
        for (int ktl = 0; ktl < 4; ktl++) {
            unsigned a[2][4];
#pragma unroll
            for (int mt = 0; mt < 2; mt++) {
                uint4 q = *(uint4*)(cur + ((wm * 2 + mt) * 4 + ktl) * 528 + lane * 16);
                a[mt][0] = q.x; a[mt][1] = q.y; a[mt][2] = q.z; a[mt][3] = q.w;
            }
            int ktg = ch * 4 + ktl;
#pragma unroll
            for (int nt2 = 0; nt2 < 4; nt2++) {
                uint4 bv = __ldg(&g_wencp4[(size_t)(ktg * 16 + wn * 4 + nt2) * 32 + lane]);
                unsigned bl[2] = {bv.x, bv.y}, bh[2] = {bv.z, bv.w};
                mma16(c[0][2*nt2],   a[0], bl);
                mma16(c[1][2*nt2],   a[1], bl);
                mma16(c[0][2*nt2+1], a[0], bh);
                mma16(c[1][2*nt2+1], a[1], bh);
            }
        }
        if (ch + 1 < T) {
            char* nxt = sSt + ((ch + 1) & 1) * 8448;
#pragma unroll
            for (int p = 0; p < 4; p++) packA(nxt, 4, rp[p], fp[p], av[p]);
        }
        __syncthreads();
    }

#pragma unroll
    for (int nt = 0; nt < 8; nt++) {
        int col = wn * 64 + nt * 8 + 2 * t;
        float b0 = __ldg(&bias[col]), b1 = __ldg(&bias[col + 1]);
#pragma unroll
        for (int mt = 0; mt < 2; mt++) {
            c[mt][nt][0] += b0; c[mt][nt][1] += b1;
            c[mt][nt][2] += b0; c[mt][nt][3] += b1;
        }
    }
#pragma unroll
    for (int mt = 0; mt < 2; mt++) {
        float s0 = 0, q0 = 0, s1v = 0, q1 = 0;
#pragma unroll
        for (int nt = 0; nt < 8; nt++) {
            s0 += c[mt][nt][0] + c[mt][nt][1];
            q0 += c[mt][nt][0] * c[mt][nt][0] + c[mt][nt][1] * c[mt][nt][1];
            s1v += c[mt][nt][2] + c[mt][nt][3];
            q1 += c[mt][nt][2] * c[mt][nt][2] + c[mt][nt][3] * c[mt][nt][3];
        }
#pragma unroll
        for (int o = 1; o <= 2; o <<= 1) {
            s0 += __shfl_xor_sync(~0u, s0, o); q0 += __shfl_xor_sync(~0u, q0, o);
            s1v += __shfl_xor_sync(~0u, s1v, o); q1 += __shfl_xor_sync(~0u, q1, o);
        }
        if (t == 0) {
            red[wn * 64 + wm * 32 + mt * 16 + g]     = make_float2(s0, q0);
            red[wn * 64 + wm * 32 + mt * 16 + g + 8] = make_float2(s1v, q1);
        }
    }
    __syncthreads();
#pragma unroll
    for (int mt = 0; mt < 2; mt++)
#pragma unroll
        for (int h = 0; h < 2; h++) {
            int row = wm * 32 + mt * 16 + g + 8 * h;
            float s = 0, q = 0;
#pragma unroll
            for (int w2 = 0; w2 < 4; w2++) {
                float2 r2 = red[w2 * 64 + row]; s += r2.x; q += r2.y;
            }
            float mu = s * (1.f / FCN);
            float rs = rsqrtf(q * (1.f / FCN) - mu * mu + 1e-5f);
#pragma unroll
            for (int nt = 0; nt < 8; nt++) {
                int col = wn * 64 + nt * 8 + 2 * t;
                float o0 = fmaxf((c[mt][nt][2*h]   - mu) * rs * __ldg(&gam[col])   + __ldg(&bet[col]),   0.f);
                float o1 = fmaxf((c[mt][nt][2*h+1] - mu) * rs * __ldg(&gam[col+1]) + __ldg(&bet[col+1]), 0.f);
                packA2(sAuv, 16, row, col, o0, o1);
                packG((R0 + row) >> 4, col >> 4, row & 15, col, packh(o0, o1));
            }
        }
    __syncthreads();

    for (int half = 0; half < 2; half++) {
        float cu[2][8][4];
#pragma unroll
        for (int mt = 0; mt < 2; mt++)
#pragma unroll
            for (int nt = 0; nt < 8; nt++)
#pragma unroll
                for (int e = 0; e < 4; e++) cu[mt][nt][e] = 0.f;

#pragma unroll 4
        for (int kt = 0; kt < 16; kt++) {
            unsigned a[2][4];
#pragma unroll
            for (int mt = 0; mt < 2; mt++) {
                uint4 q = *(uint4*)(sAuv + ((wm * 2 + mt) * 16 + kt) * 528 + lane * 16);
                a[mt][0] = q.x; a[mt][1] = q.y; a[mt][2] = q.z; a[mt][3] = q.w;
            }
#pragma unroll
            for (int nt2 = 0; nt2 < 4; nt2++) {
                uint4 bv = __ldg(&g_wuvp4[(size_t)(kt * 32 + half * 16 + wn * 4 + nt2) * 32 + lane]);
                unsigned bl[2] = {bv.x, bv.y}, bh[2] = {bv.z, bv.w};
                mma16(cu[0][2*nt2],   a[0], bl);
                mma16(cu[1][2*nt2],   a[1], bl);
                mma16(cu[0][2*nt2+1], a[0], bh);
                mma16(cu[1][2*nt2+1], a[1], bh);
            }
        }
#pragma unroll
        for (int mt = 0; mt < 2; mt++)
#pragma unroll
            for (int h = 0; h < 2; h++) {
                int row = R0 + wm * 32 + mt * 16 + g + 8 * h;
#pragma unroll
                for (int nt = 0; nt < 8; nt++) {
                    int col = half * 256 + wn * 64 + nt * 8 + 2 * t;
                    *(float2*)&g_uv[(size_t)row * 512 + col] =
                        make_float2(cu[mt][nt][2*h], cu[mt][nt][2*h+1]);
                }
            }
    }
}

// ---------------------------------------------------------------------------
// Kernel 3 (fp16): k_eff — R10 winner; effect store -> g_ap ktg 16..31.
// (unchanged from R16)
// ---------------------------------------------------------------------------
__global__ __launch_bounds__(256, 3) void k_eff(
    const float* __restrict__ core_b, const float* __restrict__ core_g,
    const float* __restrict__ core_bb,
    const float* __restrict__ ctx_b,
    const float* __restrict__ ctx_g, const float* __restrict__ ctx_bb,
    const float* __restrict__ a1_b,
    const float* __restrict__ att_g, const float* __restrict__ att_bb,
    const float* __restrict__ a2W,  const float* __restrict__ a2_b)
{
    extern __shared__ float sm[];
    char*     sAp   = (char*)sm;
    unsigned* sCtx2 = (unsigned*)(sAp + 33792);
    float2*   sRed  = (float2*)(sCtx2 + 64 * 132);
    float*    sDot  = (float*)(sRed + 4 * 64);
    float*    sAtt  = sDot + 4 * 64;
    float2*   sMu   = (float2*)(sAtt + 64);

    const int tid = threadIdx.x;
    const int wid = tid >> 5, lane = tid & 31;
    const int g = lane >> 2, t = lane & 3;
    const int wm = wid & 1, wn = wid >> 1;
    const int R0 = blockIdx.x * 56;
    const int NKT = FCN / 16;

    {
        float* z = (float*)(sAp + 3 * 16 * 528);
        for (int i = tid; i < 16 * 528 / 4; i += 256) z[i] = 0.f;
    }
    __syncthreads();

    {
#pragma unroll
        for (int rr = 0; rr < 7; rr++) {
            int lrow = wid * 7 + rr;
            int v = R0 + lrow;
            int p = v / 7;
            int jj = v - p * 7;
            int i = p & 7;
            int j = jj + (jj >= i ? 1 : 0);
            int q = (p & ~7) + j;
            float2 val[4];
            float s = 0.f, s2 = 0.f;
#pragma unroll
            for (int e = 0; e < 4; e++) {
                int col = 2 * lane + 64 * e;
                float2 u  = *(const float2*)&g_uv[(size_t)p * 512 + col];
                float2 vq = *(const float2*)&g_uv[(size_t)q * 512 + 256 + col];
                float2 cb = *(const float2*)&core_b[col];
                val[e].x = u.x + vq.x + cb.x;
                val[e].y = u.y + vq.y + cb.y;
                s += val[e].x + val[e].y;
                s2 += val[e].x * val[e].x + val[e].y * val[e].y;
            }
#pragma unroll
            for (int o = 16; o; o >>= 1) {
                s  += __shfl_xor_sync(~0u, s,  o);
                s2 += __shfl_xor_sync(~0u, s2, o);
            }
            float mu = s * (1.f / FCN);
            float rs = rsqrtf(s2 * (1.f / FCN) - mu * mu + 1e-5f);
            int mtile = lrow >> 4, gg = lrow & 7, hm = (lrow >> 3) & 1;
            int tt = lane & 3, hk = (lane >> 2) & 1;
#pragma unroll
            for (int e = 0; e < 4; e++) {
                int col = 2 * lane + 64 * e;
                float2 cg = *(const float2*)&core_g[col];
                float2 cbb = *(const float2*)&core_bb[col];
                float o0 = fmaxf((val[e].x - mu) * rs * cg.x + cbb.x, 0.f);
                float o1 = fmaxf((val[e].y - mu) * rs * cg.y + cbb.y, 0.f);
                int kt = (lane >> 3) + 4 * e;
                unsigned off = (unsigned)((mtile * 16 + kt) * 528
                                          + ((gg << 2) + tt) * 16 + (hk * 2 + hm) * 4);
                *(unsigned*)(sAp + off) = packh(o0, o1);
            }
        }
    }
    __syncthreads();

    {
        float ca[2][4][4];
#pragma unroll
        for (int mt = 0; mt < 2; mt++)
#pragma unroll
            for (int nt = 0; nt < 4; nt++)
#pragma unroll
                for (int e = 0; e < 4; e++) ca[mt][nt][e] = 0.f;

#pragma unroll
        for (int kt = 0; kt < NKT; kt++) {
            unsigned a[2][4];
#pragma unroll
            for (int mt = 0; mt < 2; mt++) {
                uint4 q = *(uint4*)(sAp + ((wm * 2 + mt) * 16 + kt) * 528 + lane * 16);
                a[mt][0] = q.x; a[mt][1] = q.y; a[mt][2] = q.z; a[mt][3] = q.w;
            }
#pragma unroll
            for (int nt2 = 0; nt2 < 2; nt2++) {
                uint4 bv = __ldg(&g_wattp4[(size_t)(kt * 8 + wn * 2 + nt2) * 32 + lane]);
                unsigned bl[2] = {bv.x, bv.y}, bh[2] = {bv.z, bv.w};
                mma16(ca[0][2*nt2],   a[0], bl);
                mma16(ca[1][2*nt2],   a[1], bl);
                mma16(ca[0][2*nt2+1], a[0], bh);
                mma16(ca[1][2*nt2+1], a[1], bh);
            }
        }
#pragma unroll
        for (int nt = 0; nt < 4; nt++) {
            int col = wn * 32 + nt * 8 + 2 * t;
            float b0 = __ldg(&a1_b[col]), b1 = __ldg(&a1_b[col + 1]);
#pragma unroll
            for (int mt = 0; mt < 2; mt++) {
                ca[mt][nt][0] += b0; ca[mt][nt][1] += b1;
                ca[mt][nt][2] += b0; ca[mt][nt][3] += b1;
            }
        }
#pragma unroll
        for (int mt = 0; mt < 2; mt++) {
            float s0 = 0, q0 = 0, s1v = 0, q1 = 0;
#pragma unroll
            for (int nt = 0; nt < 4; nt++) {
                s0 += ca[mt][nt][0] + ca[mt][nt][1];
                q0 += ca[mt][nt][0] * ca[mt][nt][0] + ca[mt][nt][1] * ca[mt][nt][1];
                s1v += ca[mt][nt][2] + ca[mt][nt][3];
                q1 += ca[mt][nt][2] * ca[mt][nt][2] + ca[mt][nt][3] * ca[mt][nt][3];
            }
#pragma unroll
            for (int o = 1; o <= 2; o <<= 1) {
                s0 += __shfl_xor_sync(~0u, s0, o); q0 += __shfl_xor_sync(~0u, q0, o);
                s1v += __shfl_xor_sync(~0u, s1v, o); q1 += __shfl_xor_sync(~0u, q1, o);
            }
            if (t == 0) {
                sRed[wn * 64 + wm * 32 + mt * 16 + g]     = make_float2(s0, q0);
                sRed[wn * 64 + wm * 32 + mt * 16 + g + 8] = make_float2(s1v, q1);
            }
        }
        __syncthreads();
#pragma unroll
        for (int mt = 0; mt < 2; mt++)
#pragma unroll
            for (int h = 0; h < 2; h++) {
                int row = wm * 32 + mt * 16 + g + 8 * h;
                float s = 0, q = 0;
#pragma unroll
                for (int w2 = 0; w2 < 4; w2++) {
                    float2 r2 = sRed[w2 * 64 + row]; s += r2.x; q += r2.y;
                }
                float mu = s * (1.f / LASTN);
                float rs = rsqrtf(q * (1.f / LASTN) - mu * mu + 1e-5f);
                float d = 0.f;
#pragma unroll
                for (int nt = 0; nt < 4; nt++) {
                    int col = wn * 32 + nt * 8 + 2 * t;
                    float gg0 = __ldg(&att_g[col]),   bb0 = __ldg(&att_bb[col]),   w0 = __ldg(&a2W[col]);
                    float gg1 = __ldg(&att_g[col+1]), bb1 = __ldg(&att_bb[col+1]), w1 = __ldg(&a2W[col+1]);
                    d += tanh_ax((ca[mt][nt][2*h]   - mu) * rs * gg0 + bb0) * w0;
                    d += tanh_ax((ca[mt][nt][2*h+1] - mu) * rs * gg1 + bb1) * w1;
                }
#pragma unroll
                for (int o = 1; o <= 2; o <<= 1) d += __shfl_xor_sync(~0u, d, o);
                if (t == 0) sDot[wn * 64 + row] = d;
            }
        __syncthreads();
        if (wid < 2) {
            int row = wid * 32 + lane;
            float a2b = __ldg(&a2_b[0]);
            float d = sDot[row] + sDot[64 + row] + sDot[128 + row] + sDot[192 + row];
            sAtt[row] = sigmoid_ax(d + a2b);
        }
        __syncthreads();
    }

    for (int half = 0; half < 2; half++) {
        float cc[2][4][4];
#pragma unroll
        for (int mt = 0; mt < 2; mt++)
#pragma unroll
            for (int nt = 0; nt < 4; nt++)
#pragma unroll
                for (int e = 0; e < 4; e++) cc[mt][nt][e] = 0.f;

#pragma unroll
        for (int kt = 0; kt < NKT; kt++) {
            unsigned a[2][4];
#pragma unroll
            for (int mt = 0; mt < 2; mt++) {
                uint4 q = *(uint4*)(sAp + ((wm * 2 + mt) * 16 + kt) * 528 + lane * 16);
                a[mt][0] = q.x; a[mt][1] = q.y; a[mt][2] = q.z; a[mt][3] = q.w;
            }
#pragma unroll
            for (int nt2 = 0; nt2 < 2; nt2++) {
                uint4 bv = __ldg(&g_wctxp4[(size_t)(kt * 16 + half * 8 + wn * 2 + nt2) * 32 + lane]);
                unsigned bl[2] = {bv.x, bv.y}, bh[2] = {bv.z, bv.w};
                mma16(cc[0][2*nt2],   a[0], bl);
                mma16(cc[1][2*nt2],   a[1], bl);
                mma16(cc[0][2*nt2+1], a[0], bh);
                mma16(cc[1][2*nt2+1], a[1], bh);
            }
        }
#pragma unroll
        for (int mt = 0; mt < 2; mt++)
#pragma unroll
            for (int nt = 0; nt < 4; nt++) {
                int col = half * 128 + wn * 32 + nt * 8 + 2 * t;
                float b0 = __ldg(&ctx_b[col]), b1 = __ldg(&ctx_b[col + 1]);
                int r0 = wm * 32 + mt * 16 + g;
                int ci = col >> 1;
                sCtx2[r0 * 132 + ci]       = packh(cc[mt][nt][0] + b0, cc[mt][nt][1] + b1);
                sCtx2[(r0 + 8) * 132 + ci] = packh(cc[mt][nt][2] + b0, cc[mt][nt][3] + b1);
            }
    }
    __syncthreads();

    {
        int r = tid >> 2, b = tid & 3;
        float s = 0.f, q = 0.f;
        if (r < 56) {
#pragma unroll
            for (int j = 0; j < 32; j++) {
                __half2 h = *(__half2*)&sCtx2[r * 132 + b + 4 * j];
                float2 f = __half22float2(h);
                s += f.x + f.y; q += f.x * f.x + f.y * f.y;
            }
        }
        s += __shfl_xor_sync(~0u, s, 1); q += __shfl_xor_sync(~0u, q, 1);
        s += __shfl_xor_sync(~0u, s, 2); q += __shfl_xor_sync(~0u, q, 2);
        if (b == 0 && r < 56) {
            float mu = s * (1.f / FCN);
            float rs = rsqrtf(q * (1.f / FCN) - mu * mu + 1e-5f);
            sMu[r] = make_float2(mu, rs);
        }
    }
    __syncthreads();

    for (int s0 = tid; s0 < 8 * 128; s0 += 256) {
        int gg = s0 >> 7, c2 = s0 & 127;
        float2 gm = __ldg((const float2*)&ctx_g[2 * c2]);
        float2 bb = __ldg((const float2*)&ctx_bb[2 * c2]);
        float e0 = 0.f, e1 = 0.f;
        int rb = gg * 7;
#pragma unroll
        for (int rr = 0; rr < 7; rr++) {
            int r = rb + rr;
            float2 mr = sMu[r];
            float at = sAtt[r];
            float2 f = __half22float2(*(__half2*)&sCtx2[r * 132 + c2]);
            e0 += fmaxf((f.x - mr.x) * mr.y * gm.x + bb.x, 0.f) * at;
            e1 += fmaxf((f.y - mr.x) * mr.y * gm.y + bb.y, 0.f) * at;
        }
        int grow = blockIdx.x * 8 + gg;
        packG(grow >> 4, 16 + (c2 >> 3), grow & 15, 2 * c2, packh(e0, e1));
    }
}

// ---------------------------------------------------------------------------
// Kernel 4 (fp16): new_state = concat(s1, effect, x) @ out_w + out_b
// R17: M=64/CTA (grid 256), uniform 96-kt loop over packed g_ap,
// register double-buffered A prefetch (distance 2), barrier-free.
// ---------------------------------------------------------------------------
__global__ __launch_bounds__(256, 2) void k_out(
    const float* __restrict__ bias, float* __restrict__ out, int dup)
{
    const int tid = threadIdx.x;
    const int wid = tid >> 5, lane = tid & 31;
    const int g = lane >> 2, t = lane & 3;
    const int wm = wid & 1, wn = wid >> 1;
    const int R0 = blockIdx.x * 64;
    const int mtg0 = (R0 >> 4) + wm * 2;
    const uint4* ap0 = &g_ap[(size_t)mtg0 * NKTG * 32 + lane];
    const uint4* ap1 = &g_ap[(size_t)(mtg0 + 1) * NKTG * 32 + lane];

    float c[2][8][4];
#pragma unroll
    for (int mt = 0; mt < 2; mt++)
#pragma unroll
        for (int nt = 0; nt < 8; nt++)
#pragma unroll
            for (int e = 0; e < 4; e++) c[mt][nt][e] = 0.f;

    // register double-buffer: qa[parity][mt] holds A fragments for ktg, ktg+1
    uint4 qa[2][2];
    qa[0][0] = __ldg(ap0);           qa[0][1] = __ldg(ap1);
    qa[1][0] = __ldg(ap0 + 32);      qa[1][1] = __ldg(ap1 + 32);

#pragma unroll 8
    for (int ktg = 0; ktg < NKTG; ktg++) {
        const int p = ktg & 1;
        unsigned a[2][4];
        a[0][0] = qa[p][0].x; a[0][1] = qa[p][0].y;
        a[0][2] = qa[p][0].z; a[0][3] = qa[p][0].w;
        a[1][0] = qa[p][1].x; a[1][1] = qa[p][1].y;
        a[1][2] = qa[p][1].z; a[1][3] = qa[p][1].w;
        if (ktg + 2 < NKTG) {
            qa[p][0] = __ldg(ap0 + (ktg + 2) * 32);
            qa[p][1] = __ldg(ap1 + (ktg + 2) * 32);
        }
#pragma unroll
        for (int nt2 = 0; nt2 < 4; nt2++) {
            uint4 bv = __ldg(&g_woutp4[(size_t)(ktg * 16 + wn * 4 + nt2) * 32 + lane]);
            unsigned bl[2] = {bv.x, bv.y}, bh[2] = {bv.z, bv.w};
            mma16(c[0][2*nt2],   a[0], bl);
            mma16(c[1][2*nt2],   a[1], bl);
            mma16(c[0][2*nt2+1], a[0], bh);
            mma16(c[1][2*nt2+1], a[1], bh);
        }
    }

#pragma unroll
    for (int mt = 0; mt < 2; mt++)
#pragma unroll
        for (int h = 0; h < 2; h++) {
            int row = R0 + (wm * 2 + mt) * 16 + g + 8 * h;
#pragma unroll
            for (int nt = 0; nt < 8; nt++) {
                int col = wn * 64 + nt * 8 + 2 * t;
                float o0 = c[mt][nt][2*h]   + __ldg(&bias[col]);
                float o1 = c[mt][nt][2*h+1] + __ldg(&bias[col + 1]);
                size_t off = (size_t)row * FCN + col;
                *(float2*)&out[off] = make_float2(o0, o1);
                if (dup) *(float2*)&out[(size_t)NR1 * FCN + off] = make_float2(o0, o1);
            }
        }
}

// ---------------------------------------------------------------------------
extern "C" void kernel_launch(void* const* d_in, const int* in_sizes, int n_in,
                              void* d_out, int out_size) {
    const float* x      = (const float*)d_in[0];
    const float* state  = (const float*)d_in[1];
    const float* enc_w  = (const float*)d_in[2];
    const float* enc_b  = (const float*)d_in[3];
    const float* enc_g  = (const float*)d_in[4];
    const float* enc_bb = (const float*)d_in[5];
    const float* core_w = (const float*)d_in[6];
    const float* core_b = (const float*)d_in[7];
    const float* core_g = (const float*)d_in[8];
    const float* core_bb= (const float*)d_in[9];
    const float* ctx_w  = (const float*)d_in[10];
    const float* ctx_b  = (const float*)d_in[11];
    const float* ctx_g  = (const float*)d_in[12];
    const float* ctx_bb = (const float*)d_in[13];
    const float* att1_w = (const float*)d_in[14];
    const float* att1_b = (const float*)d_in[15];
    const float* att_g  = (const float*)d_in[16];
    const float* att_bb = (const float*)d_in[17];
    const float* att2_w = (const float*)d_in[18];
    const float* att2_b = (const float*)d_in[19];
    const float* out_w  = (const float*)d_in[20];
    const float* out_b  = (const float*)d_in[21];
    float* out = (float*)d_out;
    int dup = (out_size >= 2 * NR1 * FCN) ? 1 : 0;

    const int smem_encuv = 33792 + 4 * 64 * 8;
    const int smem_eff   = 33792 + 33792 + 4 * 64 * 8 + 4 * 64 * 4 + 64 * 4 + 64 * 8;

    static int attr_done = 0;
    if (!attr_done) {
        cudaFuncSetAttribute(k_encuv, cudaFuncAttributeMaxDynamicSharedMemorySize, smem_encuv);
        cudaFuncSetAttribute(k_eff,   cudaFuncAttributeMaxDynamicSharedMemorySize, smem_eff);
        attr_done = 1;
    }

    k_cvtw<<<2048, 256>>>(enc_w, core_w, ctx_w, att1_w, out_w, x);
    k_encuv<<<NR1 / 64, 256, smem_encuv>>>(state, enc_b, enc_g, enc_bb);
    k_eff<<<NR2 / 56, 256, smem_eff>>>(core_b, core_g, core_bb,
                                       ctx_b, ctx_g, ctx_bb,
                                       att1_b, att_g, att_bb,
                                       att2_w, att2_b);
    k_out<<<NR1 / 64, 256>>>(out_b, out, dup);
}